// round 13
// baseline (speedup 1.0000x reference)
#include <cuda_runtime.h>
#include <cuda_fp16.h>
#include <cuda_fp8.h>

#define BB 16
#define MM 2048
#define NN 2048
#define R  16            // rows per CTA (2 chunks of 8)
#define NLAUNCH 18       // cap (fp8 convergence ~11, +2 polish, +margin)
#define TOL 1e-4f        // per-iteration relative z-change threshold
#define K8SCALE 256.f    // e4m3 storage scale (keeps K out of subnormals)

// Scratch (static __device__ globals -- no runtime allocation)
__device__ __half g_K [(size_t)BB * MM * NN];  // 134 MB fp16 kernel matrix
__device__ unsigned char g_K8[(size_t)BB * MM * NN]; // 67 MB e4m3 (256x scaled)
__device__ float  g_T[3][BB * NN];             // triple-buffered column sums
__device__ float  g_z[BB * MM];                // current z = exp(u)
__device__ float  g_ctamax[MM / R * BB];       // per-CTA max rel z-change (2048)
__device__ int    g_done_at;                   // last fp8 iteration index
__device__ int    g_finalIdx;                  // T buffer index for finalize

// ---------------------------------------------------------------------------
// T[0] = b (first iteration sees w = b/T = 1, matching v0 = 0), T[1]=T[2]=0,
// distance accumulators = 0, convergence flags reset (every graph replay).
// ---------------------------------------------------------------------------
__global__ void init_kernel(const float* __restrict__ b, float* __restrict__ out) {
    int i = blockIdx.x * blockDim.x + threadIdx.x;   // < BB*NN = 32768
    float bv = b[i];
    g_T[0][i] = bv;
    g_T[1][i] = 0.f;
    g_T[2][i] = 0.f;
    if (i < BB) out[i] = 0.f;
    if (i == 0) { g_done_at = 0x40000000; g_finalIdx = NLAUNCH % 3; }
}

// ---------------------------------------------------------------------------
// Fused build + iteration 0.  w == 1 exactly (T[0] = b):
//   read C (fp32) -> K = exp(-10 C) -> write g_K (fp16) AND g_K8 (e4m3, 256x)
//   S_i = rowsum(K);  z_i = a_i / S_i;  T[1]_j += sum_i K_ij z_i
// Grid: (MM/R, BB) = (128, 16); 512 threads.
// ---------------------------------------------------------------------------
__global__ void __launch_bounds__(512, 3)
sinkhorn_iter0(const float* __restrict__ C, const float* __restrict__ a) {
    __shared__ float part[8 * 128];
    __shared__ float zs[8];

    const int batch = blockIdx.y;
    const int rb    = blockIdx.x;
    const int tid   = threadIdx.x;
    const int warp  = tid >> 5, lane = tid & 31;
    const int row0  = rb * R;

    const float4* srcC  = (const float4*)(C + ((size_t)batch * MM + row0) * NN);
    uint2*        dstK  = (uint2*)(g_K  + ((size_t)batch * MM + row0) * NN);
    unsigned*     dstK8 = (unsigned*)(g_K8 + ((size_t)batch * MM + row0) * NN);
    float a0 = 0.f, a1 = 0.f, a2 = 0.f, a3 = 0.f;

    #pragma unroll
    for (int c = 0; c < 2; c++) {
        // Read 8 rows of C (4 fp32/thread/row), build K, keep fp16 in regs
        uint2 tile[8];
        #pragma unroll
        for (int i = 0; i < 8; i++) {
            float4 cv = srcC[(c * 8 + i) * (NN / 4) + tid];
            float e0 = __expf(-10.f * cv.x), e1 = __expf(-10.f * cv.y);
            float e2 = __expf(-10.f * cv.z), e3 = __expf(-10.f * cv.w);
            __half2 h01 = __floats2half2_rn(e0, e1);
            __half2 h23 = __floats2half2_rn(e2, e3);
            tile[i].x = *(const unsigned*)&h01;
            tile[i].y = *(const unsigned*)&h23;
            dstK[(c * 8 + i) * (NN / 4) + tid] = tile[i];
            // e4m3 copy, scaled by 256 (range [0.0116, 256] -> no subnormal loss)
            __nv_fp8x2_storage_t q01 = __nv_cvt_float2_to_fp8x2(
                make_float2(K8SCALE * e0, K8SCALE * e1), __NV_SATFINITE, __NV_E4M3);
            __nv_fp8x2_storage_t q23 = __nv_cvt_float2_to_fp8x2(
                make_float2(K8SCALE * e2, K8SCALE * e3), __NV_SATFINITE, __NV_E4M3);
            dstK8[(c * 8 + i) * (NN / 4) + tid] =
                (unsigned)q01 | ((unsigned)q23 << 16);
            // Phase 1 with w = 1: row partial is just the sum
            float v = e0 + e1 + e2 + e3;
            v += __shfl_xor_sync(0xffffffffu, v, 1);
            v += __shfl_xor_sync(0xffffffffu, v, 2);
            if ((lane & 3) == 0) part[i * 128 + (tid >> 2)] = v;
        }
        __syncthreads();

        if (warp < 8) {
            const float* pp = &part[warp * 128 + lane];
            float s = pp[0] + pp[32] + pp[64] + pp[96];
            s += __shfl_xor_sync(0xffffffffu, s, 16);
            s += __shfl_xor_sync(0xffffffffu, s, 8);
            s += __shfl_xor_sync(0xffffffffu, s, 4);
            s += __shfl_xor_sync(0xffffffffu, s, 2);
            s += __shfl_xor_sync(0xffffffffu, s, 1);
            if (lane == 0) {
                int   ri = batch * MM + row0 + c * 8 + warp;
                float zi = __fdividef(__ldg(&a[ri]), s);
                zs[warp] = zi;
                g_z[ri]  = zi;
            }
        }
        __syncthreads();

        // Phase 2: column partials from the fp16 registers
        #pragma unroll
        for (int i = 0; i < 8; i++) {
            float zi = zs[i];
            float2 f0 = __half22float2(*(const __half2*)&tile[i].x);
            float2 f1 = __half22float2(*(const __half2*)&tile[i].y);
            a0 += f0.x * zi; a1 += f0.y * zi;
            a2 += f1.x * zi; a3 += f1.y * zi;
        }
    }

    float* To = g_T[1] + batch * NN + 4 * tid;   // outIdx for k=0
    asm volatile("red.global.add.v4.f32 [%0], {%1, %2, %3, %4};"
                 :: "l"(To), "f"(a0), "f"(a1), "f"(a2), "f"(a3)
                 : "memory");
}

// ---------------------------------------------------------------------------
// One Sinkhorn iteration (k >= 1).
//   k <= done:          fp8 path (67 MB K8 stream, scale folded out exactly)
//   done < k <= done+2: fp16 polish path (pulls z,w to the fp16 fixed point)
//   k > done+2:         no-op launch
// Same two-phase register-tile dataflow in both paths; convergence detection
// (CTA (0,0), data from k-1) runs only in fp8 mode and latches done/finalIdx.
// finalIdx = done % 3 = buffer written by polish iteration done+2.
// ---------------------------------------------------------------------------
__global__ void __launch_bounds__(512, 3)
sinkhorn_iter(const float* __restrict__ a, const float* __restrict__ b, int k) {
    const int done = g_done_at;
    if (k > done + 2) return;            // converged + polished: no-op
    const bool f8 = (k <= done);

    const int inIdx   = k % 3;
    const int outIdx  = (k + 1) % 3;
    const int zeroIdx = (k + 2) % 3;

    __shared__ float part[8 * 128];
    __shared__ float zs[8];
    __shared__ float dred[16];
    __shared__ float chk[16];

    const int batch = blockIdx.y;
    const int rb    = blockIdx.x;
    const int tid   = threadIdx.x;
    const int warp  = tid >> 5, lane = tid & 31;
    const int row0  = rb * R;

    // Convergence check (fp8 mode only): reduce per-CTA maxima from k-1.
    if (f8 && rb == 0 && batch == 0 && k >= 2) {
        float m = 0.f;
        #pragma unroll
        for (int i = 0; i < 4; i++) m = fmaxf(m, g_ctamax[tid + 512 * i]);
        m = fmaxf(m, __shfl_xor_sync(0xffffffffu, m, 16));
        m = fmaxf(m, __shfl_xor_sync(0xffffffffu, m, 8));
        m = fmaxf(m, __shfl_xor_sync(0xffffffffu, m, 4));
        m = fmaxf(m, __shfl_xor_sync(0xffffffffu, m, 2));
        m = fmaxf(m, __shfl_xor_sync(0xffffffffu, m, 1));
        if (lane == 0) chk[warp] = m;
        __syncthreads();
        if (tid == 0) {
            float mm = chk[0];
            #pragma unroll
            for (int q = 1; q < 16; q++) mm = fmaxf(mm, chk[q]);
            if (mm < TOL) { g_done_at = k; g_finalIdx = k % 3; }
        }
    }

    // w for this thread's 4 contiguous columns
    float4 bv = ((const float4*)(b + batch * NN))[tid];
    float4 tv = ((const float4*)(g_T[inIdx] + batch * NN))[tid];
    const float w0 = __fdividef(bv.x, tv.x);
    const float w1 = __fdividef(bv.y, tv.y);
    const float w2 = __fdividef(bv.z, tv.z);
    const float w3 = __fdividef(bv.w, tv.w);

    // Zero slice of the buffer used two iterations from now
    if (tid < 16) g_T[zeroIdx][batch * NN + rb * 16 + tid] = 0.f;

    float a0 = 0.f, a1 = 0.f, a2 = 0.f, a3 = 0.f;

    if (f8) {
        // ---------------- fp8 path: K8 = 256*K, e4m3 -----------------------
        const unsigned* src =
            (const unsigned*)(g_K8 + ((size_t)batch * MM + row0) * NN);
        #pragma unroll
        for (int c = 0; c < 2; c++) {
            unsigned tile[8];
            #pragma unroll
            for (int i = 0; i < 8; i++)
                tile[i] = src[(c * 8 + i) * (NN / 4) + tid];

            #pragma unroll
            for (int i = 0; i < 8; i++) {
                __half2_raw r01 = __nv_cvt_fp8x2_to_halfraw2(
                    (__nv_fp8x2_storage_t)(tile[i] & 0xffffu), __NV_E4M3);
                __half2_raw r23 = __nv_cvt_fp8x2_to_halfraw2(
                    (__nv_fp8x2_storage_t)(tile[i] >> 16), __NV_E4M3);
                float2 f0 = __half22float2(*(const __half2*)&r01);
                float2 f1 = __half22float2(*(const __half2*)&r23);
                float v = f0.x * w0 + f0.y * w1 + f1.x * w2 + f1.y * w3;
                v += __shfl_xor_sync(0xffffffffu, v, 1);
                v += __shfl_xor_sync(0xffffffffu, v, 2);
                if ((lane & 3) == 0) part[i * 128 + (tid >> 2)] = v;
            }
            __syncthreads();

            if (warp < 8) {
                const float* pp = &part[warp * 128 + lane];
                float s = pp[0] + pp[32] + pp[64] + pp[96];
                s += __shfl_xor_sync(0xffffffffu, s, 16);
                s += __shfl_xor_sync(0xffffffffu, s, 8);
                s += __shfl_xor_sync(0xffffffffu, s, 4);
                s += __shfl_xor_sync(0xffffffffu, s, 2);
                s += __shfl_xor_sync(0xffffffffu, s, 1);
                if (lane == 0) {
                    int   ri = batch * MM + row0 + c * 8 + warp;
                    float zp = g_z[ri];
                    // S8 = 256*S  =>  z = 256*a / S8
                    float zi = __fdividef(K8SCALE * __ldg(&a[ri]), s);
                    zs[warp] = zi;
                    g_z[ri]  = zi;
                    dred[c * 8 + warp] = fabsf(__fdividef(zi, zp) - 1.f);
                }
            }
            __syncthreads();

            #pragma unroll
            for (int i = 0; i < 8; i++) {
                float zi = zs[i];
                __half2_raw r01 = __nv_cvt_fp8x2_to_halfraw2(
                    (__nv_fp8x2_storage_t)(tile[i] & 0xffffu), __NV_E4M3);
                __half2_raw r23 = __nv_cvt_fp8x2_to_halfraw2(
                    (__nv_fp8x2_storage_t)(tile[i] >> 16), __NV_E4M3);
                float2 f0 = __half22float2(*(const __half2*)&r01);
                float2 f1 = __half22float2(*(const __half2*)&r23);
                a0 += f0.x * zi; a1 += f0.y * zi;
                a2 += f1.x * zi; a3 += f1.y * zi;
            }
        }
        // acc holds 256*T contributions -> unscale before accumulate
        a0 *= (1.f / K8SCALE); a1 *= (1.f / K8SCALE);
        a2 *= (1.f / K8SCALE); a3 *= (1.f / K8SCALE);
    } else {
        // ---------------- fp16 polish path ---------------------------------
        const uint2* src = (const uint2*)(g_K + ((size_t)batch * MM + row0) * NN);
        #pragma unroll
        for (int c = 0; c < 2; c++) {
            uint2 tile[8];
            #pragma unroll
            for (int i = 0; i < 8; i++)
                tile[i] = src[(c * 8 + i) * (NN / 4) + tid];

            #pragma unroll
            for (int i = 0; i < 8; i++) {
                float2 f0 = __half22float2(*(const __half2*)&tile[i].x);
                float2 f1 = __half22float2(*(const __half2*)&tile[i].y);
                float v = f0.x * w0 + f0.y * w1 + f1.x * w2 + f1.y * w3;
                v += __shfl_xor_sync(0xffffffffu, v, 1);
                v += __shfl_xor_sync(0xffffffffu, v, 2);
                if ((lane & 3) == 0) part[i * 128 + (tid >> 2)] = v;
            }
            __syncthreads();

            if (warp < 8) {
                const float* pp = &part[warp * 128 + lane];
                float s = pp[0] + pp[32] + pp[64] + pp[96];
                s += __shfl_xor_sync(0xffffffffu, s, 16);
                s += __shfl_xor_sync(0xffffffffu, s, 8);
                s += __shfl_xor_sync(0xffffffffu, s, 4);
                s += __shfl_xor_sync(0xffffffffu, s, 2);
                s += __shfl_xor_sync(0xffffffffu, s, 1);
                if (lane == 0) {
                    int   ri = batch * MM + row0 + c * 8 + warp;
                    float zi = __fdividef(__ldg(&a[ri]), s);
                    zs[warp] = zi;
                    g_z[ri]  = zi;
                }
            }
            __syncthreads();

            #pragma unroll
            for (int i = 0; i < 8; i++) {
                float zi = zs[i];
                float2 f0 = __half22float2(*(const __half2*)&tile[i].x);
                float2 f1 = __half22float2(*(const __half2*)&tile[i].y);
                a0 += f0.x * zi; a1 += f0.y * zi;
                a2 += f1.x * zi; a3 += f1.y * zi;
            }
        }
    }

    float* To = g_T[outIdx] + batch * NN + 4 * tid;
    asm volatile("red.global.add.v4.f32 [%0], {%1, %2, %3, %4};"
                 :: "l"(To), "f"(a0), "f"(a1), "f"(a2), "f"(a3)
                 : "memory");

    // Publish this CTA's max rel z-change (fp8 mode; read by CTA(0,0) @ k+1)
    if (f8 && tid == 0) {
        float m = dred[0];
        #pragma unroll
        for (int q = 1; q < 16; q++) m = fmaxf(m, dred[q]);
        g_ctamax[batch * (MM / R) + rb] = m;
    }
}

// ---------------------------------------------------------------------------
// Finalize from the RESIDENT fp16 K (C is never re-read):
//   P_ij = z_i * K_ij * w_j,   C_ij = -0.1 * ln(K_ij)  (identity C = -eps lnK)
//   distance_b = sum_ij P_ij C_ij
// K >= 4.5e-5 > 0 always, so ln is safe. Thread t owns 8 cols [8t, 8t+8).
// Grid: (MM/8, BB); 256 threads; each CTA does 8 rows x 2048 cols.
// ---------------------------------------------------------------------------
__global__ void __launch_bounds__(256)
finalize_kernel(const float* __restrict__ b, float* __restrict__ out) {
    const int batch = blockIdx.y;
    const int rb    = blockIdx.x;
    const int tid   = threadIdx.x;
    const int tIdx  = g_finalIdx;

    // w for this thread's 8 contiguous columns
    const float4* b4 = (const float4*)(b + batch * NN);
    const float4* t4 = (const float4*)(g_T[tIdx] + batch * NN);
    float4 bv0 = b4[2 * tid], bv1 = b4[2 * tid + 1];
    float4 tv0 = t4[2 * tid], tv1 = t4[2 * tid + 1];
    float w[8];
    w[0] = bv0.x / tv0.x; w[1] = bv0.y / tv0.y;
    w[2] = bv0.z / tv0.z; w[3] = bv0.w / tv0.w;
    w[4] = bv1.x / tv1.x; w[5] = bv1.y / tv1.y;
    w[6] = bv1.z / tv1.z; w[7] = bv1.w / tv1.w;

    const size_t rowbase = (size_t)batch * MM + rb * 8;
    float* P = out + BB;
    float acc = 0.f;

    #pragma unroll
    for (int i = 0; i < 8; i++) {
        float zi = g_z[rowbase + i];
        uint4 kk = ((const uint4*)(g_K + (rowbase + i) * NN))[tid];  // 8 fp16
        const __half2* h = (const __half2*)&kk;
        float kf[8];
        {
            float2 f0 = __half22float2(h[0]);
            float2 f1 = __half22float2(h[1]);
            float2 f2 = __half22float2(h[2]);
            float2 f3 = __half22float2(h[3]);
            kf[0] = f0.x; kf[1] = f0.y; kf[2] = f1.x; kf[3] = f1.y;
            kf[4] = f2.x; kf[5] = f2.y; kf[6] = f3.x; kf[7] = f3.y;
        }
        float p[8];
        #pragma unroll
        for (int q = 0; q < 8; q++) {
            p[q] = zi * kf[q] * w[q];
            acc += p[q] * (-0.1f) * __logf(kf[q]);   // C = -0.1 ln K
        }
        float4* Prow = (float4*)(P + (rowbase + i) * NN);
        Prow[2 * tid]     = make_float4(p[0], p[1], p[2], p[3]);
        Prow[2 * tid + 1] = make_float4(p[4], p[5], p[6], p[7]);
    }

    // Block-reduce distance partial, one atomic per CTA per batch
    #pragma unroll
    for (int off = 16; off; off >>= 1)
        acc += __shfl_xor_sync(0xffffffffu, acc, off);
    __shared__ float rbuf[8];
    int warp = tid >> 5, lane = tid & 31;
    if (lane == 0) rbuf[warp] = acc;
    __syncthreads();
    if (tid == 0) {
        float s = 0.f;
        #pragma unroll
        for (int q = 0; q < 8; q++) s += rbuf[q];
        atomicAdd(&out[batch], s);
    }
}

// ---------------------------------------------------------------------------
extern "C" void kernel_launch(void* const* d_in, const int* in_sizes, int n_in,
                              void* d_out, int out_size) {
    const float* C = (const float*)d_in[0];   // (16, 2048, 2048)
    const float* a = (const float*)d_in[1];   // (16, 2048)
    const float* b = (const float*)d_in[2];   // (16, 2048)
    float* out = (float*)d_out;               // [0..16) distance, [16..) P

    init_kernel<<<(BB * NN) / 256, 256>>>(b, out);
    sinkhorn_iter0<<<dim3(MM / R, BB), 512>>>(C, a);
    for (int k = 1; k < NLAUNCH; k++)
        sinkhorn_iter<<<dim3(MM / R, BB), 512>>>(a, b, k);

    finalize_kernel<<<dim3(MM / 8, BB), 256>>>(b, out);
}

// round 14
// speedup vs baseline: 1.3191x; 1.3191x over previous
#include <cuda_runtime.h>
#include <cuda_fp16.h>

#define BB 16
#define MM 2048
#define NN 2048
#define R  16            // rows per CTA (2 chunks of 8)
#define NLAUNCH 16       // cap (convergence+finalize observed ~12-13)
#define TOL 1e-4f        // per-iteration relative z-change threshold
#define NOTDONE 0x40000000

// Scratch (static __device__ globals -- no runtime allocation)
__device__ __half g_K[(size_t)BB * MM * NN];   // 134 MB fp16 kernel matrix
__device__ float  g_T[3][BB * NN];             // triple-buffered column sums
__device__ float  g_z[BB * MM];                // current z = exp(u)
__device__ float  g_itermax[NLAUNCH];          // per-iteration global max rel z-change
__device__ int    g_done_at;                   // kernel index that ran the finalize
__device__ int    g_finalIdx;                  // T buffer index for FALLBACK finalize

// ---------------------------------------------------------------------------
// T[0] = b (first iteration sees w = b/T = 1, matching v0 = 0), T[1]=T[2]=0,
// distance accumulators = 0, convergence state reset (every graph replay).
// ---------------------------------------------------------------------------
__global__ void init_kernel(const float* __restrict__ b, float* __restrict__ out) {
    int i = blockIdx.x * blockDim.x + threadIdx.x;   // < BB*NN = 32768
    float bv = b[i];
    g_T[0][i] = bv;
    g_T[1][i] = 0.f;
    g_T[2][i] = 0.f;
    if (i < BB) out[i] = 0.f;
    if (i < NLAUNCH) g_itermax[i] = 0.f;
    if (i == 0) { g_done_at = NOTDONE; g_finalIdx = NLAUNCH % 3; }
}

// ---------------------------------------------------------------------------
// Fused build + iteration 0.  w == 1 exactly (T[0] = b):
//   read C (fp32) -> K = exp(-10 C) -> write g_K (fp16)
//   S_i = rowsum(K);  z_i = a_i / S_i;  T[1]_j += sum_i K_ij z_i
// Grid: (MM/R, BB) = (128, 16); 512 threads.
// ---------------------------------------------------------------------------
__global__ void __launch_bounds__(512, 3)
sinkhorn_iter0(const float* __restrict__ C, const float* __restrict__ a) {
    __shared__ float part[8 * 128];
    __shared__ float zs[8];

    const int batch = blockIdx.y;
    const int rb    = blockIdx.x;
    const int tid   = threadIdx.x;
    const int warp  = tid >> 5, lane = tid & 31;
    const int row0  = rb * R;

    const float4* srcC = (const float4*)(C + ((size_t)batch * MM + row0) * NN);
    uint2* dstK = (uint2*)(g_K + ((size_t)batch * MM + row0) * NN);
    float a0 = 0.f, a1 = 0.f, a2 = 0.f, a3 = 0.f;

    #pragma unroll
    for (int c = 0; c < 2; c++) {
        uint2 tile[8];
        #pragma unroll
        for (int i = 0; i < 8; i++) {
            float4 cv = srcC[(c * 8 + i) * (NN / 4) + tid];
            float e0 = __expf(-10.f * cv.x), e1 = __expf(-10.f * cv.y);
            float e2 = __expf(-10.f * cv.z), e3 = __expf(-10.f * cv.w);
            __half2 h01 = __floats2half2_rn(e0, e1);
            __half2 h23 = __floats2half2_rn(e2, e3);
            tile[i].x = *(const unsigned*)&h01;
            tile[i].y = *(const unsigned*)&h23;
            dstK[(c * 8 + i) * (NN / 4) + tid] = tile[i];
            float v = e0 + e1 + e2 + e3;       // w == 1
            v += __shfl_xor_sync(0xffffffffu, v, 1);
            v += __shfl_xor_sync(0xffffffffu, v, 2);
            if ((lane & 3) == 0) part[i * 128 + (tid >> 2)] = v;
        }
        __syncthreads();

        if (warp < 8) {
            const float* pp = &part[warp * 128 + lane];
            float s = pp[0] + pp[32] + pp[64] + pp[96];
            s += __shfl_xor_sync(0xffffffffu, s, 16);
            s += __shfl_xor_sync(0xffffffffu, s, 8);
            s += __shfl_xor_sync(0xffffffffu, s, 4);
            s += __shfl_xor_sync(0xffffffffu, s, 2);
            s += __shfl_xor_sync(0xffffffffu, s, 1);
            if (lane == 0) {
                int   ri = batch * MM + row0 + c * 8 + warp;
                float zi = __fdividef(__ldg(&a[ri]), s);
                zs[warp] = zi;
                g_z[ri]  = zi;
            }
        }
        __syncthreads();

        #pragma unroll
        for (int i = 0; i < 8; i++) {
            float zi = zs[i];
            float2 f0 = __half22float2(*(const __half2*)&tile[i].x);
            float2 f1 = __half22float2(*(const __half2*)&tile[i].y);
            a0 += f0.x * zi; a1 += f0.y * zi;
            a2 += f1.x * zi; a3 += f1.y * zi;
        }
    }

    float* To = g_T[1] + batch * NN + 4 * tid;   // outIdx for k=0
    asm volatile("red.global.add.v4.f32 [%0], {%1, %2, %3, %4};"
                 :: "l"(To), "f"(a0), "f"(a1), "f"(a2), "f"(a3)
                 : "memory");
}

// ---------------------------------------------------------------------------
// Kernel k >= 1.  Three modes, chosen identically by every CTA:
//   k > g_done_at:              no-op (finalize already ran)
//   k>=2 && g_itermax[k-1]<TOL: FINALIZE mode -- this kernel writes P and
//                               distance from resident fp16 K (C=-0.1 lnK),
//                               using w from T[k%3] (iter k-1's output) and z.
//   else:                       normal Gauss-Seidel iteration; publishes its
//                               global max rel z-change via one atomicMax.
// g_itermax[k-1] was fully committed by launch-boundary ordering, so all CTAs
// read the same value -> deterministic uniform branch (no intra-kernel race).
// ---------------------------------------------------------------------------
__global__ void __launch_bounds__(512, 3)
sinkhorn_iter(const float* __restrict__ a, const float* __restrict__ b,
              float* __restrict__ out, int k) {
    if (k > g_done_at) return;           // already finalized earlier

    const int inIdx   = k % 3;
    const int outIdx  = (k + 1) % 3;
    const int zeroIdx = (k + 2) % 3;
    const bool fin = (k >= 2) && (g_itermax[k - 1] < TOL);

    __shared__ float part[8 * 128];
    __shared__ float zs[8];
    __shared__ float dred[16];

    const int batch = blockIdx.y;
    const int rb    = blockIdx.x;
    const int tid   = threadIdx.x;
    const int warp  = tid >> 5, lane = tid & 31;
    const int row0  = rb * R;

    // w for this thread's 4 contiguous columns (needed by both modes)
    float4 bv = ((const float4*)(b + batch * NN))[tid];
    float4 tv = ((const float4*)(g_T[inIdx] + batch * NN))[tid];
    const float w0 = __fdividef(bv.x, tv.x);
    const float w1 = __fdividef(bv.y, tv.y);
    const float w2 = __fdividef(bv.z, tv.z);
    const float w3 = __fdividef(bv.w, tv.w);

    if (fin) {
        // ---------------- FINALIZE mode ------------------------------------
        if (tid == 0) g_done_at = k;     // same value from all CTAs: benign
        const uint2* srcK = (const uint2*)(g_K + ((size_t)batch * MM + row0) * NN);
        float* P = out + BB;
        float acc = 0.f;
        #pragma unroll
        for (int i = 0; i < R; i++) {
            float zi = __ldg(&g_z[batch * MM + row0 + i]);
            uint2 kk = srcK[i * (NN / 4) + tid];
            float2 f0 = __half22float2(*(const __half2*)&kk.x);
            float2 f1 = __half22float2(*(const __half2*)&kk.y);
            float p0 = zi * f0.x * w0, p1 = zi * f0.y * w1;
            float p2 = zi * f1.x * w2, p3 = zi * f1.y * w3;
            ((float4*)(P + ((size_t)batch * MM + row0 + i) * NN))[tid] =
                make_float4(p0, p1, p2, p3);
            acc += p0 * (-0.1f) * __logf(f0.x) + p1 * (-0.1f) * __logf(f0.y)
                 + p2 * (-0.1f) * __logf(f1.x) + p3 * (-0.1f) * __logf(f1.y);
        }
        #pragma unroll
        for (int off = 16; off; off >>= 1)
            acc += __shfl_xor_sync(0xffffffffu, acc, off);
        if (lane == 0) dred[warp] = acc;
        __syncthreads();
        if (tid == 0) {
            float s = 0.f;
            #pragma unroll
            for (int q = 0; q < 16; q++) s += dred[q];
            atomicAdd(&out[batch], s);
        }
        return;
    }

    // ---------------- normal iteration ------------------------------------
    if (tid < 16) g_T[zeroIdx][batch * NN + rb * 16 + tid] = 0.f;

    const uint2* src = (const uint2*)(g_K + ((size_t)batch * MM + row0) * NN);
    float a0 = 0.f, a1 = 0.f, a2 = 0.f, a3 = 0.f;

    #pragma unroll
    for (int c = 0; c < 2; c++) {
        uint2 tile[8];
        #pragma unroll
        for (int i = 0; i < 8; i++)
            tile[i] = src[(c * 8 + i) * (NN / 4) + tid];

        #pragma unroll
        for (int i = 0; i < 8; i++) {
            float2 f0 = __half22float2(*(const __half2*)&tile[i].x);
            float2 f1 = __half22float2(*(const __half2*)&tile[i].y);
            float v = f0.x * w0 + f0.y * w1 + f1.x * w2 + f1.y * w3;
            v += __shfl_xor_sync(0xffffffffu, v, 1);
            v += __shfl_xor_sync(0xffffffffu, v, 2);
            if ((lane & 3) == 0) part[i * 128 + (tid >> 2)] = v;
        }
        __syncthreads();

        if (warp < 8) {
            const float* pp = &part[warp * 128 + lane];
            float s = pp[0] + pp[32] + pp[64] + pp[96];
            s += __shfl_xor_sync(0xffffffffu, s, 16);
            s += __shfl_xor_sync(0xffffffffu, s, 8);
            s += __shfl_xor_sync(0xffffffffu, s, 4);
            s += __shfl_xor_sync(0xffffffffu, s, 2);
            s += __shfl_xor_sync(0xffffffffu, s, 1);
            if (lane == 0) {
                int   ri = batch * MM + row0 + c * 8 + warp;
                float zp = g_z[ri];
                float zi = __fdividef(__ldg(&a[ri]), s);
                zs[warp] = zi;
                g_z[ri]  = zi;
                dred[c * 8 + warp] = fabsf(__fdividef(zi, zp) - 1.f);
            }
        }
        __syncthreads();

        #pragma unroll
        for (int i = 0; i < 8; i++) {
            float zi = zs[i];
            float2 f0 = __half22float2(*(const __half2*)&tile[i].x);
            float2 f1 = __half22float2(*(const __half2*)&tile[i].y);
            a0 += f0.x * zi; a1 += f0.y * zi;
            a2 += f1.x * zi; a3 += f1.y * zi;
        }
    }

    float* To = g_T[outIdx] + batch * NN + 4 * tid;
    asm volatile("red.global.add.v4.f32 [%0], {%1, %2, %3, %4};"
                 :: "l"(To), "f"(a0), "f"(a1), "f"(a2), "f"(a3)
                 : "memory");

    // Publish global max rel z-change for this iteration (order-independent)
    if (tid == 0) {
        float m = dred[0];
        #pragma unroll
        for (int q = 1; q < 16; q++) m = fmaxf(m, dred[q]);
        atomicMax((int*)&g_itermax[k], __float_as_int(m));  // m >= 0
    }
}

// ---------------------------------------------------------------------------
// FALLBACK finalize (only if convergence never triggered within NLAUNCH):
// identical math to the in-iteration finalize, from resident fp16 K.
// Grid: (MM/8, BB); 256 threads.
// ---------------------------------------------------------------------------
__global__ void __launch_bounds__(256)
finalize_kernel(const float* __restrict__ b, float* __restrict__ out) {
    if (g_done_at != NOTDONE) return;    // finalize already ran in-loop

    const int batch = blockIdx.y;
    const int rb    = blockIdx.x;
    const int tid   = threadIdx.x;
    const int tIdx  = g_finalIdx;

    const float4* b4 = (const float4*)(b + batch * NN);
    const float4* t4 = (const float4*)(g_T[tIdx] + batch * NN);
    float4 bv0 = b4[2 * tid], bv1 = b4[2 * tid + 1];
    float4 tv0 = t4[2 * tid], tv1 = t4[2 * tid + 1];
    float w[8];
    w[0] = bv0.x / tv0.x; w[1] = bv0.y / tv0.y;
    w[2] = bv0.z / tv0.z; w[3] = bv0.w / tv0.w;
    w[4] = bv1.x / tv1.x; w[5] = bv1.y / tv1.y;
    w[6] = bv1.z / tv1.z; w[7] = bv1.w / tv1.w;

    const size_t rowbase = (size_t)batch * MM + rb * 8;
    float* P = out + BB;
    float acc = 0.f;

    #pragma unroll
    for (int i = 0; i < 8; i++) {
        float zi = g_z[rowbase + i];
        uint4 kk = ((const uint4*)(g_K + (rowbase + i) * NN))[tid];
        const __half2* h = (const __half2*)&kk;
        float kf[8];
        {
            float2 f0 = __half22float2(h[0]);
            float2 f1 = __half22float2(h[1]);
            float2 f2 = __half22float2(h[2]);
            float2 f3 = __half22float2(h[3]);
            kf[0] = f0.x; kf[1] = f0.y; kf[2] = f1.x; kf[3] = f1.y;
            kf[4] = f2.x; kf[5] = f2.y; kf[6] = f3.x; kf[7] = f3.y;
        }
        float p[8];
        #pragma unroll
        for (int q = 0; q < 8; q++) {
            p[q] = zi * kf[q] * w[q];
            acc += p[q] * (-0.1f) * __logf(kf[q]);
        }
        float4* Prow = (float4*)(P + (rowbase + i) * NN);
        Prow[2 * tid]     = make_float4(p[0], p[1], p[2], p[3]);
        Prow[2 * tid + 1] = make_float4(p[4], p[5], p[6], p[7]);
    }

    #pragma unroll
    for (int off = 16; off; off >>= 1)
        acc += __shfl_xor_sync(0xffffffffu, acc, off);
    __shared__ float rbuf[8];
    int warp = tid >> 5, lane = tid & 31;
    if (lane == 0) rbuf[warp] = acc;
    __syncthreads();
    if (tid == 0) {
        float s = 0.f;
        #pragma unroll
        for (int q = 0; q < 8; q++) s += rbuf[q];
        atomicAdd(&out[batch], s);
    }
}

// ---------------------------------------------------------------------------
extern "C" void kernel_launch(void* const* d_in, const int* in_sizes, int n_in,
                              void* d_out, int out_size) {
    const float* C = (const float*)d_in[0];   // (16, 2048, 2048)
    const float* a = (const float*)d_in[1];   // (16, 2048)
    const float* b = (const float*)d_in[2];   // (16, 2048)
    float* out = (float*)d_out;               // [0..16) distance, [16..) P

    init_kernel<<<(BB * NN) / 256, 256>>>(b, out);
    sinkhorn_iter0<<<dim3(MM / R, BB), 512>>>(C, a);
    for (int k = 1; k < NLAUNCH; k++)
        sinkhorn_iter<<<dim3(MM / R, BB), 512>>>(a, b, out, k);

    finalize_kernel<<<dim3(MM / 8, BB), 256>>>(b, out);
}

// round 15
// speedup vs baseline: 1.3601x; 1.0310x over previous
#include <cuda_runtime.h>
#include <cuda_fp16.h>

#define BB 16
#define MM 2048
#define NN 2048
#define R  16            // rows per CTA (2 chunks of 8)
#define NLAUNCH 16       // cap (fused convergence+finalize observed ~11-12)
#define PRETOL 2.5e-4f   // trigger: next iterate will be ~1e-4 from fixed point
#define NOTDONE 0x40000000

// Scratch (static __device__ globals -- no runtime allocation)
__device__ __half g_K[(size_t)BB * MM * NN];   // 134 MB fp16 kernel matrix
__device__ float  g_T[3][BB * NN];             // triple-buffered column sums
__device__ float  g_z[BB * MM];                // current z = exp(u)
__device__ float  g_itermax[NLAUNCH];          // per-iteration global max rel z-change
__device__ int    g_done_at;                   // kernel index that ran the fused finalize
__device__ int    g_finalIdx;                  // T buffer index for FALLBACK finalize

// ---------------------------------------------------------------------------
// T[0] = b (first iteration sees w = b/T = 1, matching v0 = 0), T[1]=T[2]=0,
// distance accumulators = 0, convergence state reset (every graph replay).
// ---------------------------------------------------------------------------
__global__ void init_kernel(const float* __restrict__ b, float* __restrict__ out) {
    int i = blockIdx.x * blockDim.x + threadIdx.x;   // < BB*NN = 32768
    float bv = b[i];
    g_T[0][i] = bv;
    g_T[1][i] = 0.f;
    g_T[2][i] = 0.f;
    if (i < BB) out[i] = 0.f;
    if (i < NLAUNCH) g_itermax[i] = 0.f;
    if (i == 0) { g_done_at = NOTDONE; g_finalIdx = NLAUNCH % 3; }
}

// ---------------------------------------------------------------------------
// Fused build + iteration 0.  w == 1 exactly (T[0] = b):
//   read C (fp32) -> K = exp(-10 C) -> write g_K (fp16)
//   S_i = rowsum(K);  z_i = a_i / S_i;  T[1]_j += sum_i K_ij z_i
// Grid: (MM/R, BB) = (128, 16); 512 threads.
// ---------------------------------------------------------------------------
__global__ void __launch_bounds__(512, 3)
sinkhorn_iter0(const float* __restrict__ C, const float* __restrict__ a) {
    __shared__ float part[8 * 128];
    __shared__ float zs[8];

    const int batch = blockIdx.y;
    const int rb    = blockIdx.x;
    const int tid   = threadIdx.x;
    const int warp  = tid >> 5, lane = tid & 31;
    const int row0  = rb * R;

    const float4* srcC = (const float4*)(C + ((size_t)batch * MM + row0) * NN);
    uint2* dstK = (uint2*)(g_K + ((size_t)batch * MM + row0) * NN);
    float a0 = 0.f, a1 = 0.f, a2 = 0.f, a3 = 0.f;

    #pragma unroll
    for (int c = 0; c < 2; c++) {
        uint2 tile[8];
        #pragma unroll
        for (int i = 0; i < 8; i++) {
            float4 cv = srcC[(c * 8 + i) * (NN / 4) + tid];
            float e0 = __expf(-10.f * cv.x), e1 = __expf(-10.f * cv.y);
            float e2 = __expf(-10.f * cv.z), e3 = __expf(-10.f * cv.w);
            __half2 h01 = __floats2half2_rn(e0, e1);
            __half2 h23 = __floats2half2_rn(e2, e3);
            tile[i].x = *(const unsigned*)&h01;
            tile[i].y = *(const unsigned*)&h23;
            dstK[(c * 8 + i) * (NN / 4) + tid] = tile[i];
            float v = e0 + e1 + e2 + e3;       // w == 1
            v += __shfl_xor_sync(0xffffffffu, v, 1);
            v += __shfl_xor_sync(0xffffffffu, v, 2);
            if ((lane & 3) == 0) part[i * 128 + (tid >> 2)] = v;
        }
        __syncthreads();

        if (warp < 8) {
            const float* pp = &part[warp * 128 + lane];
            float s = pp[0] + pp[32] + pp[64] + pp[96];
            s += __shfl_xor_sync(0xffffffffu, s, 16);
            s += __shfl_xor_sync(0xffffffffu, s, 8);
            s += __shfl_xor_sync(0xffffffffu, s, 4);
            s += __shfl_xor_sync(0xffffffffu, s, 2);
            s += __shfl_xor_sync(0xffffffffu, s, 1);
            if (lane == 0) {
                int   ri = batch * MM + row0 + c * 8 + warp;
                float zi = __fdividef(__ldg(&a[ri]), s);
                zs[warp] = zi;
                g_z[ri]  = zi;
            }
        }
        __syncthreads();

        #pragma unroll
        for (int i = 0; i < 8; i++) {
            float zi = zs[i];
            float2 f0 = __half22float2(*(const __half2*)&tile[i].x);
            float2 f1 = __half22float2(*(const __half2*)&tile[i].y);
            a0 += f0.x * zi; a1 += f0.y * zi;
            a2 += f1.x * zi; a3 += f1.y * zi;
        }
    }

    float* To = g_T[1] + batch * NN + 4 * tid;   // outIdx for k=0
    asm volatile("red.global.add.v4.f32 [%0], {%1, %2, %3, %4};"
                 :: "l"(To), "f"(a0), "f"(a1), "f"(a2), "f"(a3)
                 : "memory");
}

// ---------------------------------------------------------------------------
// Kernel k >= 1.  Three modes, chosen identically by every CTA:
//   k > g_done_at:                 no-op (fused finalize already ran)
//   k>=2 && g_itermax[k-1]<PRETOL: FUSED mode -- phase 1 computes fresh z from
//                                  w_in, then the SAME register tile writes
//                                  P = z_new*K*w_in and accumulates
//                                  distance = sum P*(-0.1 lnK). One K pass.
//   else:                          normal Gauss-Seidel iteration; publishes
//                                  global max rel z-change via one atomicMax.
// g_itermax[k-1] is committed by launch-boundary ordering -> all CTAs take the
// same branch deterministically.
// ---------------------------------------------------------------------------
__global__ void __launch_bounds__(512, 3)
sinkhorn_iter(const float* __restrict__ a, const float* __restrict__ b,
              float* __restrict__ out, int k) {
    if (k > g_done_at) return;           // already finalized earlier

    const int inIdx   = k % 3;
    const int outIdx  = (k + 1) % 3;
    const int zeroIdx = (k + 2) % 3;
    const bool fin = (k >= 2) && (g_itermax[k - 1] < PRETOL);

    __shared__ float part[8 * 128];
    __shared__ float zs[8];
    __shared__ float dred[16];

    const int batch = blockIdx.y;
    const int rb    = blockIdx.x;
    const int tid   = threadIdx.x;
    const int warp  = tid >> 5, lane = tid & 31;
    const int row0  = rb * R;

    // w for this thread's 4 contiguous columns
    float4 bv = ((const float4*)(b + batch * NN))[tid];
    float4 tv = ((const float4*)(g_T[inIdx] + batch * NN))[tid];
    const float w0 = __fdividef(bv.x, tv.x);
    const float w1 = __fdividef(bv.y, tv.y);
    const float w2 = __fdividef(bv.z, tv.z);
    const float w3 = __fdividef(bv.w, tv.w);

    // Zero next-next T buffer (only needed if we keep iterating)
    if (!fin && tid < 16) g_T[zeroIdx][batch * NN + rb * 16 + tid] = 0.f;

    const uint2* src = (const uint2*)(g_K + ((size_t)batch * MM + row0) * NN);
    float a0 = 0.f, a1 = 0.f, a2 = 0.f, a3 = 0.f;   // T partials OR distance acc
    float dist = 0.f;
    float* P = out + BB;

    #pragma unroll
    for (int c = 0; c < 2; c++) {
        uint2 tile[8];
        #pragma unroll
        for (int i = 0; i < 8; i++)
            tile[i] = src[(c * 8 + i) * (NN / 4) + tid];

        // Phase 1: row dots with w_in, 4-lane pre-reduce
        #pragma unroll
        for (int i = 0; i < 8; i++) {
            float2 f0 = __half22float2(*(const __half2*)&tile[i].x);
            float2 f1 = __half22float2(*(const __half2*)&tile[i].y);
            float v = f0.x * w0 + f0.y * w1 + f1.x * w2 + f1.y * w3;
            v += __shfl_xor_sync(0xffffffffu, v, 1);
            v += __shfl_xor_sync(0xffffffffu, v, 2);
            if ((lane & 3) == 0) part[i * 128 + (tid >> 2)] = v;
        }
        __syncthreads();

        // One warp per row: S_i -> z_i (fresh, from w_in)
        if (warp < 8) {
            const float* pp = &part[warp * 128 + lane];
            float s = pp[0] + pp[32] + pp[64] + pp[96];
            s += __shfl_xor_sync(0xffffffffu, s, 16);
            s += __shfl_xor_sync(0xffffffffu, s, 8);
            s += __shfl_xor_sync(0xffffffffu, s, 4);
            s += __shfl_xor_sync(0xffffffffu, s, 2);
            s += __shfl_xor_sync(0xffffffffu, s, 1);
            if (lane == 0) {
                int   ri = batch * MM + row0 + c * 8 + warp;
                float zp = g_z[ri];
                float zi = __fdividef(__ldg(&a[ri]), s);
                zs[warp] = zi;
                g_z[ri]  = zi;
                dred[c * 8 + warp] = fabsf(__fdividef(zi, zp) - 1.f);
            }
        }
        __syncthreads();

        if (fin) {
            // FUSED finalize: P = z_new * K * w_in, distance from C = -0.1 lnK
            #pragma unroll
            for (int i = 0; i < 8; i++) {
                float zi = zs[i];
                float2 f0 = __half22float2(*(const __half2*)&tile[i].x);
                float2 f1 = __half22float2(*(const __half2*)&tile[i].y);
                float p0 = zi * f0.x * w0, p1 = zi * f0.y * w1;
                float p2 = zi * f1.x * w2, p3 = zi * f1.y * w3;
                ((float4*)(P + ((size_t)batch * MM + row0 + c * 8 + i) * NN))[tid] =
                    make_float4(p0, p1, p2, p3);
                dist += p0 * __logf(f0.x) + p1 * __logf(f0.y)
                      + p2 * __logf(f1.x) + p3 * __logf(f1.y);
            }
        } else {
            // Phase 2: column partials from the same registers
            #pragma unroll
            for (int i = 0; i < 8; i++) {
                float zi = zs[i];
                float2 f0 = __half22float2(*(const __half2*)&tile[i].x);
                float2 f1 = __half22float2(*(const __half2*)&tile[i].y);
                a0 += f0.x * zi; a1 += f0.y * zi;
                a2 += f1.x * zi; a3 += f1.y * zi;
            }
        }
    }

    if (fin) {
        // distance partial: multiply by -0.1 once, block-reduce, one atomic
        dist *= -0.1f;
        #pragma unroll
        for (int off = 16; off; off >>= 1)
            dist += __shfl_xor_sync(0xffffffffu, dist, off);
        __shared__ float rbuf[16];
        if (lane == 0) rbuf[warp] = dist;
        __syncthreads();
        if (tid == 0) {
            float s = 0.f;
            #pragma unroll
            for (int q = 0; q < 16; q++) s += rbuf[q];
            atomicAdd(&out[batch], s);
            g_done_at = k;               // same value from all CTAs: benign
        }
        return;
    }

    float* To = g_T[outIdx] + batch * NN + 4 * tid;
    asm volatile("red.global.add.v4.f32 [%0], {%1, %2, %3, %4};"
                 :: "l"(To), "f"(a0), "f"(a1), "f"(a2), "f"(a3)
                 : "memory");

    // Publish global max rel z-change for this iteration (order-independent)
    if (tid == 0) {
        float m = dred[0];
        #pragma unroll
        for (int q = 1; q < 16; q++) m = fmaxf(m, dred[q]);
        atomicMax((int*)&g_itermax[k], __float_as_int(m));  // m >= 0
    }
}

// ---------------------------------------------------------------------------
// FALLBACK finalize (only if convergence never triggered within NLAUNCH):
// P from resident fp16 K with w = b/T[finalIdx], z from g_z; C = -0.1 lnK.
// Grid: (MM/8, BB); 256 threads.
// ---------------------------------------------------------------------------
__global__ void __launch_bounds__(256)
finalize_kernel(const float* __restrict__ b, float* __restrict__ out) {
    if (g_done_at != NOTDONE) return;    // fused finalize already ran

    const int batch = blockIdx.y;
    const int rb    = blockIdx.x;
    const int tid   = threadIdx.x;
    const int tIdx  = g_finalIdx;

    const float4* b4 = (const float4*)(b + batch * NN);
    const float4* t4 = (const float4*)(g_T[tIdx] + batch * NN);
    float4 bv0 = b4[2 * tid], bv1 = b4[2 * tid + 1];
    float4 tv0 = t4[2 * tid], tv1 = t4[2 * tid + 1];
    float w[8];
    w[0] = bv0.x / tv0.x; w[1] = bv0.y / tv0.y;
    w[2] = bv0.z / tv0.z; w[3] = bv0.w / tv0.w;
    w[4] = bv1.x / tv1.x; w[5] = bv1.y / tv1.y;
    w[6] = bv1.z / tv1.z; w[7] = bv1.w / tv1.w;

    const size_t rowbase = (size_t)batch * MM + rb * 8;
    float* P = out + BB;
    float acc = 0.f;

    #pragma unroll
    for (int i = 0; i < 8; i++) {
        float zi = g_z[rowbase + i];
        uint4 kk = ((const uint4*)(g_K + (rowbase + i) * NN))[tid];
        const __half2* h = (const __half2*)&kk;
        float kf[8];
        {
            float2 f0 = __half22float2(h[0]);
            float2 f1 = __half22float2(h[1]);
            float2 f2 = __half22float2(h[2]);
            float2 f3 = __half22float2(h[3]);
            kf[0] = f0.x; kf[1] = f0.y; kf[2] = f1.x; kf[3] = f1.y;
            kf[4] = f2.x; kf[5] = f2.y; kf[6] = f3.x; kf[7] = f3.y;
        }
        float p[8];
        #pragma unroll
        for (int q = 0; q < 8; q++) {
            p[q] = zi * kf[q] * w[q];
            acc += p[q] * (-0.1f) * __logf(kf[q]);
        }
        float4* Prow = (float4*)(P + (rowbase + i) * NN);
        Prow[2 * tid]     = make_float4(p[0], p[1], p[2], p[3]);
        Prow[2 * tid + 1] = make_float4(p[4], p[5], p[6], p[7]);
    }

    #pragma unroll
    for (int off = 16; off; off >>= 1)
        acc += __shfl_xor_sync(0xffffffffu, acc, off);
    __shared__ float rbuf[8];
    int warp = tid >> 5, lane = tid & 31;
    if (lane == 0) rbuf[warp] = acc;
    __syncthreads();
    if (tid == 0) {
        float s = 0.f;
        #pragma unroll
        for (int q = 0; q < 8; q++) s += rbuf[q];
        atomicAdd(&out[batch], s);
    }
}

// ---------------------------------------------------------------------------
extern "C" void kernel_launch(void* const* d_in, const int* in_sizes, int n_in,
                              void* d_out, int out_size) {
    const float* C = (const float*)d_in[0];   // (16, 2048, 2048)
    const float* a = (const float*)d_in[1];   // (16, 2048)
    const float* b = (const float*)d_in[2];   // (16, 2048)
    float* out = (float*)d_out;               // [0..16) distance, [16..) P

    init_kernel<<<(BB * NN) / 256, 256>>>(b, out);
    sinkhorn_iter0<<<dim3(MM / R, BB), 512>>>(C, a);
    for (int k = 1; k < NLAUNCH; k++)
        sinkhorn_iter<<<dim3(MM / R, BB), 512>>>(a, b, out, k);

    finalize_kernel<<<dim3(MM / 8, BB), 256>>>(b, out);
}